// round 2
// baseline (speedup 1.0000x reference)
#include <cuda_runtime.h>

#define B_   1024
#define D_   64
#define H_   256
#define G4   1024      // 4*H
#define T_   128
#define A_   8
#define MB   8         // batch rows per CTA
#define NCTA (B_ / MB) // 128

// ----------------- static device scratch (no allocations allowed) ----------
__device__ float g_WT0[H_ * G4];       // W_hh0^T as [k][j][gate]
__device__ float g_WT1[2 * H_ * G4];   // [W_ih1; W_hh1]^T as [k][j][gate], k<256 -> ih1
__device__ float g_b1[G4];             // (b_ih1 + b_hh1) as [j][gate]
__device__ float g_gx0[B_ * G4];       // xn @ W_ih0^T + b_ih0 + b_hh0, as [b][j][gate]

typedef unsigned long long u64;

// ----------------- packed f32x2 helpers (sm_103a FFMA2) --------------------
__device__ __forceinline__ u64 ffma2(u64 a, u64 b, u64 c) {
    u64 d;
    asm("fma.rn.f32x2 %0, %1, %2, %3;" : "=l"(d) : "l"(a), "l"(b), "l"(c));
    return d;
}
__device__ __forceinline__ u64 pk2(float lo, float hi) {
    u64 r;
    asm("mov.b64 %0, {%1, %2};" : "=l"(r) : "f"(lo), "f"(hi));
    return r;
}
__device__ __forceinline__ void up2(u64 v, float& lo, float& hi) {
    asm("mov.b64 {%0, %1}, %2;" : "=f"(lo), "=f"(hi) : "l"(v));
}

// ----------------- activations (fp32, ~1e-7 rel) ---------------------------
__device__ __forceinline__ float sigf(float x) {
    return __fdividef(1.0f, 1.0f + __expf(-x));
}
__device__ __forceinline__ float tanhf_(float x) {
    return 1.0f - __fdividef(2.0f, __expf(2.0f * x) + 1.0f);
}

// ============================================================================
// Prep 1: transpose recurrent weights into [k][j][gate], fold layer-1 biases
// ============================================================================
__global__ void prep_weights(const float* __restrict__ Whh0,
                             const float* __restrict__ Wih1,
                             const float* __restrict__ Whh1,
                             const float* __restrict__ bih1,
                             const float* __restrict__ bhh1)
{
    const int idx = blockIdx.x * blockDim.x + threadIdx.x;
    const int stride = gridDim.x * blockDim.x;
    for (int i = idx; i < H_ * G4; i += stride) {
        const int gate = i & 3, j = (i >> 2) & (H_ - 1), k = i >> 10;
        g_WT0[i] = Whh0[(gate * H_ + j) * H_ + k];
    }
    for (int i = idx; i < 2 * H_ * G4; i += stride) {
        const int gate = i & 3, j = (i >> 2) & (H_ - 1), k = i >> 10;
        const int n = gate * H_ + j;
        g_WT1[i] = (k < H_) ? Wih1[n * H_ + k] : Whh1[n * H_ + (k - H_)];
    }
    for (int i = idx; i < G4; i += stride) {
        const int gate = i & 3, j = i >> 2;
        const int n = gate * H_ + j;
        g_b1[i] = bih1[n] + bhh1[n];
    }
}

// ============================================================================
// Prep 2: layernorm(state) then gx0 = xn @ W_ih0^T + (b_ih0 + b_hh0)
// One CTA per batch row, 256 threads.
// ============================================================================
__global__ void prep_gx0(const float* __restrict__ state,
                         const float* __restrict__ gamma,
                         const float* __restrict__ beta,
                         const float* __restrict__ Wih0,
                         const float* __restrict__ bih0,
                         const float* __restrict__ bhh0)
{
    const int b = blockIdx.x;
    const int t = threadIdx.x;
    __shared__ float xs[D_];
    __shared__ float xn[D_];

    if (t < D_) xs[t] = state[b * D_ + t];
    __syncthreads();

    // redundant per-thread mean/var over 64 elems (cheap, broadcast reads)
    float mu = 0.f;
    #pragma unroll
    for (int k = 0; k < D_; k++) mu += xs[k];
    mu *= (1.0f / D_);
    float var = 0.f;
    #pragma unroll
    for (int k = 0; k < D_; k++) { const float d = xs[k] - mu; var += d * d; }
    var *= (1.0f / D_);
    const float rs = rsqrtf(var + 1e-5f);

    if (t < D_) xn[t] = (xs[t] - mu) * rs * gamma[t] + beta[t];
    __syncthreads();

    #pragma unroll
    for (int g = 0; g < 4; g++) {
        const int n = g * H_ + t;
        const float* w = Wih0 + n * D_;
        float acc = bih0[n] + bhh0[n];
        #pragma unroll
        for (int k = 0; k < D_; k++) acc += xn[k] * w[k];
        g_gx0[(b * H_ + t) * 4 + g] = acc;
    }
}

// ============================================================================
// Main recurrence: 128 CTAs x 256 threads. CTA owns 8 batch rows; thread t
// owns hidden index j=t of both layers. c-states live in registers all T steps.
// ============================================================================
__global__ void __launch_bounds__(256, 1)
lstm_main(const float* __restrict__ fcW,
          const float* __restrict__ fcb,
          float* __restrict__ out)
{
    __shared__ float2 sh_h0[MB][H_];   // (h,h) duplicated for f32x2 operands
    __shared__ float2 sh_h1[MB][H_];
    __shared__ float  sh_fc[A_ * H_];
    __shared__ float  sh_fcb[A_];

    const int t = threadIdx.x;
    const int b0 = blockIdx.x * MB;

    for (int i = t; i < A_ * H_; i += 256) sh_fc[i] = fcW[i];
    if (t < A_) sh_fcb[t] = fcb[t];
    #pragma unroll
    for (int r = 0; r < MB; r++) {
        sh_h0[r][t] = make_float2(0.f, 0.f);
        sh_h1[r][t] = make_float2(0.f, 0.f);
    }

    // time-invariant layer-0 gate bias (per batch row) and layer-1 bias
    u64 gx_if[MB], gx_go[MB];
    #pragma unroll
    for (int r = 0; r < MB; r++) {
        const float4 g = *(const float4*)(g_gx0 + ((b0 + r) * H_ + t) * 4);
        gx_if[r] = pk2(g.x, g.y);
        gx_go[r] = pk2(g.z, g.w);
    }
    u64 b1_if, b1_go;
    {
        const float4 g = *(const float4*)(g_b1 + t * 4);
        b1_if = pk2(g.x, g.y);
        b1_go = pk2(g.z, g.w);
    }

    float c0[MB], c1[MB];
    #pragma unroll
    for (int r = 0; r < MB; r++) { c0[r] = 0.f; c1[r] = 0.f; }

    __syncthreads();

    for (int step = 0; step < T_; step++) {
        u64 aif[MB], ago[MB];

        // ---------------- layer 0 gates: h0_old @ W_hh0^T + gx0 ------------
        #pragma unroll
        for (int r = 0; r < MB; r++) { aif[r] = gx_if[r]; ago[r] = gx_go[r]; }
        {
            const float* w0 = g_WT0 + t * 4;
            #pragma unroll 4
            for (int k = 0; k < H_; k++) {
                const ulonglong2 w = *(const ulonglong2*)(w0 + k * G4);
                #pragma unroll
                for (int r = 0; r < MB; r++) {
                    const u64 h2 = *(const u64*)&sh_h0[r][k];
                    aif[r] = ffma2(h2, w.x, aif[r]);
                    ago[r] = ffma2(h2, w.y, ago[r]);
                }
            }
        }
        // cell 0 (register-local)
        float hn0[MB];
        #pragma unroll
        for (int r = 0; r < MB; r++) {
            float gi, gf, gg, go;
            up2(aif[r], gi, gf);
            up2(ago[r], gg, go);
            const float cn = sigf(gf) * c0[r] + sigf(gi) * tanhf_(gg);
            c0[r] = cn;
            hn0[r] = sigf(go) * tanhf_(cn);
        }
        __syncthreads();
        #pragma unroll
        for (int r = 0; r < MB; r++) sh_h0[r][t] = make_float2(hn0[r], hn0[r]);
        __syncthreads();

        // ---------- layer 1 gates: h0_new @ W_ih1^T + h1_old @ W_hh1^T + b1 -
        #pragma unroll
        for (int r = 0; r < MB; r++) { aif[r] = b1_if; ago[r] = b1_go; }
        {
            const float* w1 = g_WT1 + t * 4;
            #pragma unroll 4
            for (int k = 0; k < H_; k++) {
                const ulonglong2 w = *(const ulonglong2*)(w1 + k * G4);
                #pragma unroll
                for (int r = 0; r < MB; r++) {
                    const u64 h2 = *(const u64*)&sh_h0[r][k];
                    aif[r] = ffma2(h2, w.x, aif[r]);
                    ago[r] = ffma2(h2, w.y, ago[r]);
                }
            }
            const float* w1b = g_WT1 + H_ * G4 + t * 4;
            #pragma unroll 4
            for (int k = 0; k < H_; k++) {
                const ulonglong2 w = *(const ulonglong2*)(w1b + k * G4);
                #pragma unroll
                for (int r = 0; r < MB; r++) {
                    const u64 h2 = *(const u64*)&sh_h1[r][k];
                    aif[r] = ffma2(h2, w.x, aif[r]);
                    ago[r] = ffma2(h2, w.y, ago[r]);
                }
            }
        }
        // cell 1
        float hn1[MB];
        #pragma unroll
        for (int r = 0; r < MB; r++) {
            float gi, gf, gg, go;
            up2(aif[r], gi, gf);
            up2(ago[r], gg, go);
            const float cn = sigf(gf) * c1[r] + sigf(gi) * tanhf_(gg);
            c1[r] = cn;
            hn1[r] = sigf(go) * tanhf_(cn);
        }
        __syncthreads();
        #pragma unroll
        for (int r = 0; r < MB; r++) sh_h1[r][t] = make_float2(hn1[r], hn1[r]);
        __syncthreads();

        // ---------------- FC head: action = tanh(h1 @ fcW^T + fcb) ---------
        {
            const int row  = t >> 5;       // batch row within CTA (8 warps)
            const int lane = t & 31;
            const int a    = lane >> 2;    // action index 0..7
            const int part = lane & 3;     // k-split 0..3 (64 each)
            const float* hrow = (const float*)&sh_h1[row][0]; // stride-2 floats
            const float* wrow = sh_fc + a * H_ + part * 64;
            float acc = 0.f;
            #pragma unroll 8
            for (int jj = 0; jj < 64; jj++)
                acc += hrow[(part * 64 + jj) * 2] * wrow[jj];
            acc += __shfl_xor_sync(0xffffffffu, acc, 1);
            acc += __shfl_xor_sync(0xffffffffu, acc, 2);
            if (part == 0)
                out[((b0 + row) * T_ + step) * A_ + a] = tanhf_(acc + sh_fcb[a]);
        }
    }
}

// ============================================================================
extern "C" void kernel_launch(void* const* d_in, const int* in_sizes, int n_in,
                              void* d_out, int out_size)
{
    const float* state = (const float*)d_in[0];
    const float* gamma = (const float*)d_in[1];
    const float* beta  = (const float*)d_in[2];
    const float* Wih0  = (const float*)d_in[3];
    const float* Whh0  = (const float*)d_in[4];
    const float* bih0  = (const float*)d_in[5];
    const float* bhh0  = (const float*)d_in[6];
    const float* Wih1  = (const float*)d_in[7];
    const float* Whh1  = (const float*)d_in[8];
    const float* bih1  = (const float*)d_in[9];
    const float* bhh1  = (const float*)d_in[10];
    const float* fcW   = (const float*)d_in[11];
    const float* fcb   = (const float*)d_in[12];
    float* out = (float*)d_out;

    prep_weights<<<264, 256>>>(Whh0, Wih1, Whh1, bih1, bhh1);
    prep_gx0<<<B_, 256>>>(state, gamma, beta, Wih0, bih0, bhh0);
    lstm_main<<<NCTA, 256>>>(fcW, fcb, out);
}

// round 3
// speedup vs baseline: 1.3209x; 1.3209x over previous
#include <cuda_runtime.h>

#define B_   1024
#define D_   64
#define H_   256
#define G4   1024      // 4*H
#define T_   128
#define A_   8
#define GRID 148       // CTAs for main kernel (<= SM count; balanced 6/7 rows)

// ----------------- static device scratch (no allocations allowed) ----------
// packed weights: [kpair][j][gate][e] , e = k parity  (8 floats per (kpair,j))
__device__ float g_WT0p[128 * H_ * 8];        // W_hh0^T packed   (1 MB)
__device__ float g_WT1p[256 * H_ * 8];        // [W_ih1;W_hh1]^T packed (2 MB)
__device__ float g_b1[G4];                    // (b_ih1+b_hh1) as [j][gate]
__device__ float g_gx0[B_ * G4];              // xn@W_ih0^T + b0, as [b][j][gate]

typedef unsigned long long u64;

// ----------------- packed f32x2 helpers (sm_103a FFMA2) --------------------
__device__ __forceinline__ u64 ffma2(u64 a, u64 b, u64 c) {
    u64 d;
    asm("fma.rn.f32x2 %0, %1, %2, %3;" : "=l"(d) : "l"(a), "l"(b), "l"(c));
    return d;
}
__device__ __forceinline__ float hadd2(u64 v) {
    float lo, hi;
    asm("mov.b64 {%0, %1}, %2;" : "=f"(lo), "=f"(hi) : "l"(v));
    return lo + hi;
}

// ----------------- activations (fp32, ~1e-7 rel) ---------------------------
__device__ __forceinline__ float sigf(float x) {
    return __fdividef(1.0f, 1.0f + __expf(-x));
}
__device__ __forceinline__ float tanhf_(float x) {
    return 1.0f - __fdividef(2.0f, __expf(2.0f * x) + 1.0f);
}

// ============================================================================
// Prep 1: repack recurrent weights into [kpair][j][gate][e], fold L1 biases
// ============================================================================
__global__ void prep_weights(const float* __restrict__ Whh0,
                             const float* __restrict__ Wih1,
                             const float* __restrict__ Whh1,
                             const float* __restrict__ bih1,
                             const float* __restrict__ bhh1)
{
    const int idx = blockIdx.x * blockDim.x + threadIdx.x;
    const int stride = gridDim.x * blockDim.x;
    for (int i = idx; i < 128 * H_ * 8; i += stride) {
        const int e = i & 1, g = (i >> 1) & 3, j = (i >> 3) & (H_ - 1), p = i >> 11;
        const int k = 2 * p + e;
        g_WT0p[i] = Whh0[(g * H_ + j) * H_ + k];
    }
    for (int i = idx; i < 256 * H_ * 8; i += stride) {
        const int e = i & 1, g = (i >> 1) & 3, j = (i >> 3) & (H_ - 1), p = i >> 11;
        const int k = 2 * p + e;
        const int n = g * H_ + j;
        g_WT1p[i] = (k < H_) ? Wih1[n * H_ + k] : Whh1[n * H_ + (k - H_)];
    }
    for (int i = idx; i < G4; i += stride) {
        const int g = i & 3, j = i >> 2;
        g_b1[i] = bih1[g * H_ + j] + bhh1[g * H_ + j];
    }
}

// ============================================================================
// Prep 2: layernorm(state) then gx0 = xn @ W_ih0^T + (b_ih0 + b_hh0)
// ============================================================================
__global__ void prep_gx0(const float* __restrict__ state,
                         const float* __restrict__ gamma,
                         const float* __restrict__ beta,
                         const float* __restrict__ Wih0,
                         const float* __restrict__ bih0,
                         const float* __restrict__ bhh0)
{
    const int b = blockIdx.x;
    const int t = threadIdx.x;
    __shared__ float xs[D_];
    __shared__ float xn[D_];

    if (t < D_) xs[t] = state[b * D_ + t];
    __syncthreads();

    float mu = 0.f;
    #pragma unroll
    for (int k = 0; k < D_; k++) mu += xs[k];
    mu *= (1.0f / D_);
    float var = 0.f;
    #pragma unroll
    for (int k = 0; k < D_; k++) { const float d = xs[k] - mu; var += d * d; }
    var *= (1.0f / D_);
    const float rs = rsqrtf(var + 1e-5f);

    if (t < D_) xn[t] = (xs[t] - mu) * rs * gamma[t] + beta[t];
    __syncthreads();

    #pragma unroll
    for (int g = 0; g < 4; g++) {
        const int n = g * H_ + t;
        const float* w = Wih0 + n * D_;
        float acc = bih0[n] + bhh0[n];
        #pragma unroll
        for (int k = 0; k < D_; k++) acc += xn[k] * w[k];
        g_gx0[(b * H_ + t) * 4 + g] = acc;
    }
}

// ============================================================================
// Main recurrence. GRID CTAs x 256 threads; CTA owns MBT (6 or 7) batch rows,
// thread t owns hidden index j=t of both layers. c-states stay in registers.
// f32x2 lanes = even/odd-k partial sums; h in plain-float shared (LDS.64 per
// k-pair per row), weights 32B/thread/kpair coalesced from L2.
// ============================================================================
template <int MBT>
__device__ __forceinline__ void run_lstm(
    const int b0, const int t,
    float (&sh0)[2][7][H_], float (&sh1)[2][7][H_],
    const float* __restrict__ sfc, const float* __restrict__ sfcb,
    float* __restrict__ out)
{
    #pragma unroll
    for (int r = 0; r < MBT; r++) { sh0[0][r][t] = 0.f; sh1[0][r][t] = 0.f; }

    // time-invariant gate biases
    float gx[MBT][4];
    #pragma unroll
    for (int r = 0; r < MBT; r++) {
        const float4 g = *(const float4*)(g_gx0 + ((b0 + r) * H_ + t) * 4);
        gx[r][0] = g.x; gx[r][1] = g.y; gx[r][2] = g.z; gx[r][3] = g.w;
    }
    float b1v[4];
    {
        const float4 g = *(const float4*)(g_b1 + t * 4);
        b1v[0] = g.x; b1v[1] = g.y; b1v[2] = g.z; b1v[3] = g.w;
    }

    float c0[MBT], c1[MBT];
    #pragma unroll
    for (int r = 0; r < MBT; r++) { c0[r] = 0.f; c1[r] = 0.f; }

    __syncthreads();

    const ulonglong2* __restrict__ w0p = ((const ulonglong2*)g_WT0p) + t * 2;
    const ulonglong2* __restrict__ w1p = ((const ulonglong2*)g_WT1p) + t * 2;

    int pb = 0;
    for (int step = 0; step < T_; step++, pb ^= 1) {
        // ---------------- layer 0: h0_old @ W_hh0^T ------------------------
        u64 acc[MBT][4];
        #pragma unroll
        for (int r = 0; r < MBT; r++)
            #pragma unroll
            for (int g = 0; g < 4; g++) acc[r][g] = 0ull;

        #pragma unroll 4
        for (int p = 0; p < 128; p++) {
            const ulonglong2 wA = __ldg(w0p + p * 512);      // gates 0,1
            const ulonglong2 wB = __ldg(w0p + p * 512 + 1);  // gates 2,3
            #pragma unroll
            for (int r = 0; r < MBT; r++) {
                const u64 h2 = *(const u64*)&sh0[pb][r][2 * p];
                acc[r][0] = ffma2(h2, wA.x, acc[r][0]);
                acc[r][1] = ffma2(h2, wA.y, acc[r][1]);
                acc[r][2] = ffma2(h2, wB.x, acc[r][2]);
                acc[r][3] = ffma2(h2, wB.y, acc[r][3]);
            }
        }
        #pragma unroll
        for (int r = 0; r < MBT; r++) {
            const float gi = hadd2(acc[r][0]) + gx[r][0];
            const float gf = hadd2(acc[r][1]) + gx[r][1];
            const float gg = hadd2(acc[r][2]) + gx[r][2];
            const float go = hadd2(acc[r][3]) + gx[r][3];
            const float cn = sigf(gf) * c0[r] + sigf(gi) * tanhf_(gg);
            c0[r] = cn;
            sh0[pb ^ 1][r][t] = sigf(go) * tanhf_(cn);
        }
        __syncthreads();

        // -------- layer 1: h0_new @ W_ih1^T + h1_old @ W_hh1^T --------------
        #pragma unroll
        for (int r = 0; r < MBT; r++)
            #pragma unroll
            for (int g = 0; g < 4; g++) acc[r][g] = 0ull;

        #pragma unroll 4
        for (int p = 0; p < 128; p++) {
            const ulonglong2 wA = __ldg(w1p + p * 512);
            const ulonglong2 wB = __ldg(w1p + p * 512 + 1);
            #pragma unroll
            for (int r = 0; r < MBT; r++) {
                const u64 h2 = *(const u64*)&sh0[pb ^ 1][r][2 * p];
                acc[r][0] = ffma2(h2, wA.x, acc[r][0]);
                acc[r][1] = ffma2(h2, wA.y, acc[r][1]);
                acc[r][2] = ffma2(h2, wB.x, acc[r][2]);
                acc[r][3] = ffma2(h2, wB.y, acc[r][3]);
            }
        }
        #pragma unroll 4
        for (int p = 0; p < 128; p++) {
            const ulonglong2 wA = __ldg(w1p + (128 + p) * 512);
            const ulonglong2 wB = __ldg(w1p + (128 + p) * 512 + 1);
            #pragma unroll
            for (int r = 0; r < MBT; r++) {
                const u64 h2 = *(const u64*)&sh1[pb][r][2 * p];
                acc[r][0] = ffma2(h2, wA.x, acc[r][0]);
                acc[r][1] = ffma2(h2, wA.y, acc[r][1]);
                acc[r][2] = ffma2(h2, wB.x, acc[r][2]);
                acc[r][3] = ffma2(h2, wB.y, acc[r][3]);
            }
        }
        #pragma unroll
        for (int r = 0; r < MBT; r++) {
            const float gi = hadd2(acc[r][0]) + b1v[0];
            const float gf = hadd2(acc[r][1]) + b1v[1];
            const float gg = hadd2(acc[r][2]) + b1v[2];
            const float go = hadd2(acc[r][3]) + b1v[3];
            const float cn = sigf(gf) * c1[r] + sigf(gi) * tanhf_(gg);
            c1[r] = cn;
            sh1[pb ^ 1][r][t] = sigf(go) * tanhf_(cn);
        }
        __syncthreads();

        // ---------------- FC head: tanh(h1 @ fcW^T + fcb) ------------------
        {
            const int row  = t >> 5;
            const int lane = t & 31;
            const int a    = lane >> 2;
            const int part = lane & 3;
            if (row < MBT) {
                const float* hrow = &sh1[pb ^ 1][row][0];
                const float* wrow = sfc + a * H_ + part * 64;
                float accf = 0.f;
                #pragma unroll 8
                for (int jj = 0; jj < 64; jj++)
                    accf += hrow[part * 64 + jj] * wrow[jj];
                accf += __shfl_xor_sync(0xffffffffu, accf, 1);
                accf += __shfl_xor_sync(0xffffffffu, accf, 2);
                if (part == 0)
                    out[((b0 + row) * T_ + step) * A_ + a] =
                        tanhf_(accf + sfcb[a]);
            }
        }
    }
}

__global__ void __launch_bounds__(256, 1)
lstm_main(const float* __restrict__ fcW,
          const float* __restrict__ fcb,
          float* __restrict__ out)
{
    __shared__ float sh0[2][7][H_];
    __shared__ float sh1[2][7][H_];
    __shared__ float sfc[A_ * H_];
    __shared__ float sfcb[A_];

    const int t = threadIdx.x;
    for (int i = t; i < A_ * H_; i += 256) sfc[i] = fcW[i];
    if (t < A_) sfcb[t] = fcb[t];

    const int b0  = (blockIdx.x * B_) / GRID;
    const int cnt = ((blockIdx.x + 1) * B_) / GRID - b0;

    if (cnt == 7) run_lstm<7>(b0, t, sh0, sh1, sfc, sfcb, out);
    else          run_lstm<6>(b0, t, sh0, sh1, sfc, sfcb, out);
}

// ============================================================================
extern "C" void kernel_launch(void* const* d_in, const int* in_sizes, int n_in,
                              void* d_out, int out_size)
{
    const float* state = (const float*)d_in[0];
    const float* gamma = (const float*)d_in[1];
    const float* beta  = (const float*)d_in[2];
    const float* Wih0  = (const float*)d_in[3];
    const float* Whh0  = (const float*)d_in[4];
    const float* bih0  = (const float*)d_in[5];
    const float* bhh0  = (const float*)d_in[6];
    const float* Wih1  = (const float*)d_in[7];
    const float* Whh1  = (const float*)d_in[8];
    const float* bih1  = (const float*)d_in[9];
    const float* bhh1  = (const float*)d_in[10];
    const float* fcW   = (const float*)d_in[11];
    const float* fcb   = (const float*)d_in[12];
    float* out = (float*)d_out;

    prep_weights<<<264, 256>>>(Whh0, Wih1, Whh1, bih1, bhh1);
    prep_gx0<<<B_, 256>>>(state, gamma, beta, Wih0, bih0, bhh0);
    lstm_main<<<GRID, 256>>>(fcW, fcb, out);
}